// round 5
// baseline (speedup 1.0000x reference)
#include <cuda_runtime.h>
#include <cuda_fp16.h>
#include <cstdint>

#define N_DRUG 846
#define DIM 256
#define KNB 128

// ---------------- scratch (device globals; no allocation allowed) -------------
__device__ float g_b2sum[KNB];
__device__ float g_lpart[N_DRUG * 256];     // [n][half][128]
__device__ float g_weighted[N_DRUG * DIM];
__device__ float g_x[N_DRUG * DIM];
__device__ float g_sum[DIM];
__device__ float g_sumsq[DIM];

// ---------------- warp-level mma + ldmatrix (baseline PTX) --------------------
__device__ __forceinline__ void mma16816(float* c, const uint32_t* a,
                                         uint32_t b0, uint32_t b1) {
    asm volatile(
        "mma.sync.aligned.m16n8k16.row.col.f32.f16.f16.f32 "
        "{%0,%1,%2,%3}, {%4,%5,%6,%7}, {%8,%9}, {%0,%1,%2,%3};"
        : "+f"(c[0]), "+f"(c[1]), "+f"(c[2]), "+f"(c[3])
        : "r"(a[0]), "r"(a[1]), "r"(a[2]), "r"(a[3]), "r"(b0), "r"(b1));
}
__device__ __forceinline__ void ldmx4(uint32_t* r, uint32_t addr) {
    asm volatile(
        "ldmatrix.sync.aligned.m8n8.x4.shared.b16 {%0,%1,%2,%3}, [%4];"
        : "=r"(r[0]), "=r"(r[1]), "=r"(r[2]), "=r"(r[3]) : "r"(addr));
}
__device__ __forceinline__ uint32_t smem_u32(const void* p) {
    uint32_t a;
    asm("{ .reg .u64 t; cvta.to.shared.u64 t, %1; cvt.u32.u64 %0, t; }"
        : "=r"(a) : "l"(p));
    return a;
}

// ---------------- k0: b2sum[k] = sum_e b2[k,e] --------------------------------
__global__ void k_init(const float* __restrict__ b2) {
    int t = threadIdx.x;
    int w = t >> 5, lane = t & 31;
    for (int k = w; k < KNB; k += 8) {
        const float4* row = reinterpret_cast<const float4*>(b2 + k * DIM);
        float4 a = row[lane];
        float4 bq = row[lane + 32];
        float s = a.x + a.y + a.z + a.w + bq.x + bq.y + bq.z + bq.w;
        #pragma unroll
        for (int m = 16; m; m >>= 1) s += __shfl_xor_sync(0xffffffffu, s, m);
        if (lane == 0) g_b2sum[k] = s;
    }
}

// ---------------- k2: partial logits via fp16-split mma.sync + fused w2sum ----
static constexpr int ROWB = 144;
static constexpr int A_HI = 0;
static constexpr int A_LO = A_HI + 128 * ROWB;
static constexpr int B_HI = A_LO + 128 * ROWB;
static constexpr int B_LO = B_HI + 128 * ROWB;
static constexpr int SM_DRUG = B_LO + 128 * ROWB;   // 256 f32
static constexpr int SM_W2 = SM_DRUG + 1024;        // 128 f32
static constexpr int SM_REL = SM_W2 + 512;          // 128 int
static constexpr int SM_LP = SM_REL + 512;          // 128 f32
static constexpr int SMEM_TOTAL = SM_LP + 512;

__global__ void __launch_bounds__(256, 2) k_logits(
    const int* __restrict__ drug_name, const int* __restrict__ adj_rel,
    const float* __restrict__ drug_table, const float* __restrict__ rela_table,
    const float* __restrict__ W1, const float* __restrict__ b1p,
    const float* __restrict__ W2) {
    extern __shared__ char smem[];
    float* s_drug = (float*)(smem + SM_DRUG);
    float* s_w2 = (float*)(smem + SM_W2);
    int* s_rel = (int*)(smem + SM_REL);
    float* s_lp = (float*)(smem + SM_LP);

    int n = blockIdx.x, eh = blockIdx.y;
    int e0 = eh * 128;
    int tid = threadIdx.x;
    int wid = tid >> 5, lane = tid & 31;
    int g = lane >> 2, tg = lane & 3;
    int m0 = (wid & 3) * 32;
    int n0 = (wid >> 2) * 64;

    int dn = drug_name[n];
    s_drug[tid] = drug_table[dn * DIM + tid];
    if (tid < KNB) {
        s_rel[tid] = adj_rel[n * KNB + tid];
        s_lp[tid] = 0.f;
    }
    __syncthreads();

    const float* W1n = W1 + (size_t)n * (DIM * DIM);
    const float* W2n = W2 + (size_t)n * (DIM * DIM);

    uint32_t sbase = smem_u32(smem);
    // ldmatrix lane-address offsets (per warp)
    int lr = lane & 7;
    uint32_t a_off = sbase + A_HI +
                     (uint32_t)(m0 + lr + ((lane >> 3) & 1) * 8) * ROWB +
                     (lane >> 4) * 16;
    uint32_t b_off = sbase + B_HI +
                     (uint32_t)(n0 + lr + (lane >> 4) * 8) * ROWB +
                     ((lane >> 3) & 1) * 16;
    const uint32_t LO_OFF = 128 * ROWB;  // A_LO-A_HI == B_LO-B_HI

    float c[2][8][4];
    #pragma unroll
    for (int mt = 0; mt < 2; mt++)
        #pragma unroll
        for (int nt = 0; nt < 8; nt++)
            #pragma unroll
            for (int q = 0; q < 4; q++) c[mt][nt][q] = 0.f;

    for (int ch = 0; ch < 4; ch++) {
        int dc = ch * 64;
        if (ch) __syncthreads();

        // ---- stage A chunk: split drug*rela into hi/lo fp16
        #pragma unroll
        for (int it = 0; it < 16; it++) {
            int idx = tid + it * 256;
            int k = idx >> 5;
            int dd = (idx & 31) * 2;
            float2 rv = *(const float2*)(rela_table + (size_t)s_rel[k] * DIM + dc + dd);
            float a0 = s_drug[dc + dd] * rv.x;
            float a1 = s_drug[dc + dd + 1] * rv.y;
            __half h0 = __float2half_rn(a0), h1 = __float2half_rn(a1);
            float l0 = a0 - __half2float(h0), l1 = a1 - __half2float(h1);
            *(__half2*)(smem + A_HI + k * ROWB + dd * 2) = __halves2half2(h0, h1);
            *(__half2*)(smem + A_LO + k * ROWB + dd * 2) =
                __halves2half2(__float2half_rn(l0), __float2half_rn(l1));
        }
        // ---- stage B chunk: W1n[dc+dd][e0+e] split
        #pragma unroll
        for (int it = 0; it < 16; it++) {
            int idx = tid + it * 256;
            int e = idx & 127;
            int dd = (idx >> 7) * 2;
            const float* wp = W1n + (size_t)(dc + dd) * DIM + e0 + e;
            float w0 = wp[0], w1 = wp[DIM];
            __half h0 = __float2half_rn(w0), h1 = __float2half_rn(w1);
            float l0 = w0 - __half2float(h0), l1 = w1 - __half2float(h1);
            *(__half2*)(smem + B_HI + e * ROWB + dd * 2) = __halves2half2(h0, h1);
            *(__half2*)(smem + B_LO + e * ROWB + dd * 2) =
                __halves2half2(__float2half_rn(l0), __float2half_rn(l1));
        }
        __syncthreads();

        // ---- MMA phase: 4 k16-steps, term-major ordering
        #pragma unroll
        for (int ks = 0; ks < 4; ks++) {
            uint32_t kb = ks * 32;
            uint32_t ah[2][4], al[2][4], bb[4][4];
            ldmx4(ah[0], a_off + kb);
            ldmx4(ah[1], a_off + 16 * ROWB + kb);
            #pragma unroll
            for (int np = 0; np < 4; np++)
                ldmx4(bb[np], b_off + np * 16 * ROWB + kb);
            #pragma unroll
            for (int np = 0; np < 4; np++) {
                mma16816(c[0][2 * np], ah[0], bb[np][0], bb[np][1]);
                mma16816(c[0][2 * np + 1], ah[0], bb[np][2], bb[np][3]);
                mma16816(c[1][2 * np], ah[1], bb[np][0], bb[np][1]);
                mma16816(c[1][2 * np + 1], ah[1], bb[np][2], bb[np][3]);
            }
            ldmx4(al[0], a_off + LO_OFF + kb);
            ldmx4(al[1], a_off + LO_OFF + 16 * ROWB + kb);
            #pragma unroll
            for (int np = 0; np < 4; np++) {
                mma16816(c[0][2 * np], al[0], bb[np][0], bb[np][1]);
                mma16816(c[0][2 * np + 1], al[0], bb[np][2], bb[np][3]);
                mma16816(c[1][2 * np], al[1], bb[np][0], bb[np][1]);
                mma16816(c[1][2 * np + 1], al[1], bb[np][2], bb[np][3]);
            }
            #pragma unroll
            for (int np = 0; np < 4; np++)
                ldmx4(bb[np], b_off + LO_OFF + np * 16 * ROWB + kb);
            #pragma unroll
            for (int np = 0; np < 4; np++) {
                mma16816(c[0][2 * np], ah[0], bb[np][0], bb[np][1]);
                mma16816(c[0][2 * np + 1], ah[0], bb[np][2], bb[np][3]);
                mma16816(c[1][2 * np], ah[1], bb[np][0], bb[np][1]);
                mma16816(c[1][2 * np + 1], ah[1], bb[np][2], bb[np][3]);
            }
        }

        // ---- fused w2sum ROW-sums: warp reduces 4 rows per chunk (coalesced)
        #pragma unroll
        for (int j = 0; j < 4; j++) {
            int row = wid * 16 + ch * 4 + j;                 // local e-row 0..127
            const float4* rp =
                reinterpret_cast<const float4*>(W2n + (size_t)(e0 + row) * DIM);
            float4 a = __ldg(rp + lane);
            float4 b = __ldg(rp + lane + 32);
            float s = (a.x + a.y + a.z + a.w) + (b.x + b.y + b.z + b.w);
            #pragma unroll
            for (int m = 16; m; m >>= 1) s += __shfl_xor_sync(0xffffffffu, s, m);
            if (lane == 0) s_w2[row] = s;
        }
    }
    __syncthreads();

    // ---- epilogue: +b1, relu, dot w2sum; deterministic reduction
    float lg[2][2] = {{0.f, 0.f}, {0.f, 0.f}};
    #pragma unroll
    for (int mt = 0; mt < 2; mt++) {
        int r0 = m0 + mt * 16 + g;
        #pragma unroll
        for (int nt = 0; nt < 8; nt++) {
            int ecl = n0 + nt * 8 + tg * 2;
            float w0 = s_w2[ecl], w1 = s_w2[ecl + 1];
            float2 b00 = *(const float2*)(b1p + (size_t)r0 * DIM + e0 + ecl);
            float2 b01 = *(const float2*)(b1p + (size_t)(r0 + 8) * DIM + e0 + ecl);
            lg[mt][0] += fmaxf(c[mt][nt][0] + b00.x, 0.f) * w0 +
                         fmaxf(c[mt][nt][1] + b00.y, 0.f) * w1;
            lg[mt][1] += fmaxf(c[mt][nt][2] + b01.x, 0.f) * w0 +
                         fmaxf(c[mt][nt][3] + b01.y, 0.f) * w1;
        }
    }
    #pragma unroll
    for (int mt = 0; mt < 2; mt++)
        #pragma unroll
        for (int h = 0; h < 2; h++) {
            float v = lg[mt][h];
            v += __shfl_xor_sync(0xffffffffu, v, 1);
            v += __shfl_xor_sync(0xffffffffu, v, 2);
            if (tg == 0)
                atomicAdd(&s_lp[m0 + mt * 16 + h * 8 + g], v);  // 2 contributors
        }
    __syncthreads();
    if (tid < KNB) g_lpart[n * 256 + eh * 128 + tid] = s_lp[tid];
}

// ---------------- k3: softmax + weighted entity gather (4-way k-sliced) -------
__global__ void __launch_bounds__(1024) k_softgather(
    const int* __restrict__ adj_tail, const float* __restrict__ ent_table) {
    __shared__ float s_logit[KNB];
    __shared__ int s_tail[KNB];
    __shared__ float s_red[32];
    __shared__ float s_scalar;
    __shared__ float s_acc[1024];
    int n = blockIdx.x, tid = threadIdx.x;
    int wid = tid >> 5, lane = tid & 31;

    if (tid < KNB) {
        s_logit[tid] = g_lpart[n * 256 + tid] + g_lpart[n * 256 + 128 + tid] +
                       g_b2sum[tid];
        s_tail[tid] = adj_tail[n * KNB + tid];
    }
    __syncthreads();

    float v = (tid < KNB) ? s_logit[tid] : -1e30f;
    #pragma unroll
    for (int m = 16; m; m >>= 1) v = fmaxf(v, __shfl_xor_sync(0xffffffffu, v, m));
    if (lane == 0) s_red[wid] = v;
    __syncthreads();
    if (tid == 0) {
        float mm = s_red[0];
        #pragma unroll
        for (int i = 1; i < 32; i++) mm = fmaxf(mm, s_red[i]);
        s_scalar = mm;
    }
    __syncthreads();
    float mm = s_scalar;
    float ev = (tid < KNB) ? expf(s_logit[tid] - mm) : 0.f;
    float sv = ev;
    #pragma unroll
    for (int m = 16; m; m >>= 1) sv += __shfl_xor_sync(0xffffffffu, sv, m);
    if (lane == 0) s_red[wid] = sv;
    __syncthreads();
    if (tid == 0) {
        float ss = 0.f;
        #pragma unroll
        for (int i = 0; i < 32; i++) ss += s_red[i];
        s_scalar = 1.f / ss;
    }
    __syncthreads();
    if (tid < KNB) s_logit[tid] = ev * s_scalar;
    __syncthreads();

    int d = tid & 255, sl = tid >> 8;
    float wacc = 0.f;
    #pragma unroll 8
    for (int k = sl * 32; k < sl * 32 + 32; k++)
        wacc += s_logit[k] * __ldg(&ent_table[(size_t)s_tail[k] * DIM + d]);
    s_acc[tid] = wacc;
    __syncthreads();
    if (tid < 256)
        g_weighted[n * DIM + tid] =
            (s_acc[tid] + s_acc[tid + 256]) + (s_acc[tid + 512] + s_acc[tid + 768]);
}

// ---------------- k4: x = relu([weighted, drug] @ lin_w^T + lin_b) ------------
static constexpr int LIN_ROWS = 12;
static constexpr int SMEM_LIN = (LIN_ROWS * 512 + 256 * 33) * 4;

__global__ void __launch_bounds__(256) k_linear(
    const int* __restrict__ drug_name, const float* __restrict__ drug_table,
    const float* __restrict__ lin_w, const float* __restrict__ lin_b) {
    extern __shared__ float lsm[];
    float (*s_in)[512] = (float(*)[512])lsm;
    float (*s_w)[33] = (float(*)[33])(lsm + LIN_ROWS * 512);
    int tid = threadIdx.x;
    int n0 = blockIdx.x * LIN_ROWS;

    #pragma unroll
    for (int p = 0; p < 2 * LIN_ROWS; p++) {
        int idx = tid + p * 256;
        int b = idx >> 9, i = idx & 511;
        int nn = n0 + b;
        if (nn > N_DRUG - 1) nn = N_DRUG - 1;
        float val;
        if (i < 256) val = g_weighted[nn * DIM + i];
        else val = drug_table[drug_name[nn] * DIM + (i - 256)];
        s_in[b][i] = val;
    }

    float acc[LIN_ROWS];
    #pragma unroll
    for (int b = 0; b < LIN_ROWS; b++) acc[b] = 0.f;

    for (int i0 = 0; i0 < 512; i0 += 32) {
        __syncthreads();
        #pragma unroll
        for (int p = 0; p < 32; p++) {
            int j = (tid >> 5) + p * 8;
            int ii = tid & 31;
            s_w[j][ii] = lin_w[j * 512 + i0 + ii];
        }
        __syncthreads();
        #pragma unroll
        for (int ii = 0; ii < 32; ii++) {
            float w = s_w[tid][ii];
            #pragma unroll
            for (int b = 0; b < LIN_ROWS; b++) acc[b] += s_in[b][i0 + ii] * w;
        }
    }
    float bj = lin_b[tid];
    #pragma unroll
    for (int b = 0; b < LIN_ROWS; b++) {
        int nn = n0 + b;
        if (nn < N_DRUG) g_x[nn * DIM + tid] = fmaxf(acc[b] + bj, 0.f);
    }
}

// ---------------- k4b: deterministic BN statistics ----------------------------
__global__ void __launch_bounds__(256) k_bnstat() {
    __shared__ float ss[256], sq[256];
    int j = blockIdx.x, tid = threadIdx.x;
    float s = 0.f, q = 0.f;
    for (int nn = tid; nn < N_DRUG; nn += 256) {
        float v = g_x[nn * DIM + j];
        s += v;
        q += v * v;
    }
    ss[tid] = s;
    sq[tid] = q;
    __syncthreads();
    #pragma unroll
    for (int off = 128; off; off >>= 1) {
        if (tid < off) {
            ss[tid] += ss[tid + off];
            sq[tid] += sq[tid + off];
        }
        __syncthreads();
    }
    if (tid == 0) {
        g_sum[j] = ss[0];
        g_sumsq[j] = sq[0];
    }
}

// ---------------- k5: BatchNorm finalize --------------------------------------
__global__ void k_bn(const float* __restrict__ gamma, const float* __restrict__ beta,
                     float* __restrict__ out) {
    int n = blockIdx.x, j = threadIdx.x;
    const float inv_n = 1.f / 846.f;
    float mean = g_sum[j] * inv_n;
    float var = g_sumsq[j] * inv_n - mean * mean;
    float rstd = rsqrtf(var + 1e-5f);
    out[n * DIM + j] = gamma[j] * (g_x[n * DIM + j] - mean) * rstd + beta[j];
}

// ---------------- launch -------------------------------------------------------
extern "C" void kernel_launch(void* const* d_in, const int* in_sizes, int n_in,
                              void* d_out, int out_size) {
    const int* drug_name = (const int*)d_in[0];
    const int* adj_tail = (const int*)d_in[1];
    const int* adj_rel = (const int*)d_in[2];
    const float* drug_table = (const float*)d_in[3];
    const float* rela_table = (const float*)d_in[4];
    const float* ent_table = (const float*)d_in[5];
    const float* W1 = (const float*)d_in[6];
    const float* b1 = (const float*)d_in[7];
    const float* W2 = (const float*)d_in[8];
    const float* b2 = (const float*)d_in[9];
    const float* lin_w = (const float*)d_in[10];
    const float* lin_b = (const float*)d_in[11];
    const float* gamma = (const float*)d_in[12];
    const float* beta = (const float*)d_in[13];
    float* out = (float*)d_out;

    cudaFuncSetAttribute(k_logits, cudaFuncAttributeMaxDynamicSharedMemorySize,
                         SMEM_TOTAL);
    cudaFuncSetAttribute(k_linear, cudaFuncAttributeMaxDynamicSharedMemorySize,
                         SMEM_LIN);

    k_init<<<1, 256>>>(b2);
    dim3 grid_l(N_DRUG, 2);
    k_logits<<<grid_l, 256, SMEM_TOTAL>>>(drug_name, adj_rel, drug_table,
                                          rela_table, W1, b1, W2);
    k_softgather<<<N_DRUG, 1024>>>(adj_tail, ent_table);
    k_linear<<<(N_DRUG + LIN_ROWS - 1) / LIN_ROWS, 256, SMEM_LIN>>>(
        drug_name, drug_table, lin_w, lin_b);
    k_bnstat<<<256, 256>>>();
    k_bn<<<N_DRUG, 256>>>(gamma, beta, out);
}

// round 6
// speedup vs baseline: 1.0315x; 1.0315x over previous
#include <cuda_runtime.h>
#include <cuda_fp16.h>
#include <cstdint>

#define N_DRUG 846
#define DIM 256
#define KNB 128

// ---------------- scratch (device globals; no allocation allowed) -------------
__device__ float g_b2sum[KNB];
__device__ float g_lpart[N_DRUG * 256];     // [n][half][128]
__device__ float g_weighted[N_DRUG * DIM];
__device__ float g_x[N_DRUG * DIM];
__device__ float g_sum[DIM];
__device__ float g_sumsq[DIM];

// ---------------- warp-level mma + ldmatrix (baseline PTX) --------------------
__device__ __forceinline__ void mma16816(float* c, const uint32_t* a,
                                         uint32_t b0, uint32_t b1) {
    asm volatile(
        "mma.sync.aligned.m16n8k16.row.col.f32.f16.f16.f32 "
        "{%0,%1,%2,%3}, {%4,%5,%6,%7}, {%8,%9}, {%0,%1,%2,%3};"
        : "+f"(c[0]), "+f"(c[1]), "+f"(c[2]), "+f"(c[3])
        : "r"(a[0]), "r"(a[1]), "r"(a[2]), "r"(a[3]), "r"(b0), "r"(b1));
}
__device__ __forceinline__ void ldmx4(uint32_t* r, uint32_t addr) {
    asm volatile(
        "ldmatrix.sync.aligned.m8n8.x4.shared.b16 {%0,%1,%2,%3}, [%4];"
        : "=r"(r[0]), "=r"(r[1]), "=r"(r[2]), "=r"(r[3]) : "r"(addr));
}
__device__ __forceinline__ uint32_t smem_u32(const void* p) {
    uint32_t a;
    asm("{ .reg .u64 t; cvta.to.shared.u64 t, %1; cvt.u32.u64 %0, t; }"
        : "=r"(a) : "l"(p));
    return a;
}

// ---------------- k0: b2sum[k] = sum_e b2[k,e] --------------------------------
__global__ void k_init(const float* __restrict__ b2) {
    int t = threadIdx.x;
    int w = t >> 5, lane = t & 31;
    for (int k = w; k < KNB; k += 8) {
        const float4* row = reinterpret_cast<const float4*>(b2 + k * DIM);
        float4 a = row[lane];
        float4 bq = row[lane + 32];
        float s = a.x + a.y + a.z + a.w + bq.x + bq.y + bq.z + bq.w;
        #pragma unroll
        for (int m = 16; m; m >>= 1) s += __shfl_xor_sync(0xffffffffu, s, m);
        if (lane == 0) g_b2sum[k] = s;
    }
}

// ---------------- k2: pipelined fp16-split mma.sync + fused w2sum -------------
static constexpr int ROWB = 144;
static constexpr int A_HI = 0;
static constexpr int A_LO = 128 * ROWB;          // 18432
static constexpr int B_HI = 2 * 128 * ROWB;      // 36864
static constexpr int B_LO = 3 * 128 * ROWB;      // 55296
static constexpr int BUFSZ = 4 * 128 * ROWB;     // 73728
static constexpr int MISC = 2 * BUFSZ;           // 147456
static constexpr int SM_DRUG = MISC;             // 256 f32
static constexpr int SM_W2 = MISC + 1024;        // 128 f32
static constexpr int SM_REL = MISC + 1536;       // 128 int
static constexpr int SM_LP = MISC + 2048;        // 128 f32
static constexpr int SMEM_TOTAL = MISC + 2560;   // 150016 B

__global__ void __launch_bounds__(256, 1) k_logits(
    const int* __restrict__ drug_name, const int* __restrict__ adj_rel,
    const float* __restrict__ drug_table, const float* __restrict__ rela_table,
    const float* __restrict__ W1, const float* __restrict__ b1p,
    const float* __restrict__ W2) {
    extern __shared__ char smem[];
    float* s_drug = (float*)(smem + SM_DRUG);
    float* s_w2 = (float*)(smem + SM_W2);
    int* s_rel = (int*)(smem + SM_REL);
    float* s_lp = (float*)(smem + SM_LP);

    int n = blockIdx.x, eh = blockIdx.y;
    int e0 = eh * 128;
    int tid = threadIdx.x;
    int wid = tid >> 5, lane = tid & 31;
    int g = lane >> 2, tg = lane & 3;
    int m0 = (wid & 3) * 32;
    int n0 = (wid >> 2) * 64;

    int dn = drug_name[n];
    s_drug[tid] = drug_table[dn * DIM + tid];
    if (tid < KNB) {
        s_rel[tid] = adj_rel[n * KNB + tid];
        s_lp[tid] = 0.f;
    }
    __syncthreads();

    const float* W1n = W1 + (size_t)n * (DIM * DIM);
    const float* W2n = W2 + (size_t)n * (DIM * DIM);

    uint32_t sbase = smem_u32(smem);
    int lr = lane & 7;
    uint32_t a_base = sbase + A_HI +
                      (uint32_t)(m0 + lr + ((lane >> 3) & 1) * 8) * ROWB +
                      (lane >> 4) * 16;
    uint32_t b_base = sbase + B_HI +
                      (uint32_t)(n0 + lr + (lane >> 4) * 8) * ROWB +
                      ((lane >> 3) & 1) * 16;
    const uint32_t LO_OFF = 128 * ROWB;

    // prefetch mappings
    int ka = tid >> 1;                 // A: row
    int dh = (tid & 1) * 32;           // A: d-offset half
    const float* arow = rela_table + (size_t)s_rel[ka] * DIM + dh;
    int eb = tid & 127;                // B: e column
    int db = (tid >> 7) * 2;           // B: dd base (0 or 2), step 4

    float4 af4[8];
    float bf[32];

    // ---- P(0): prefetch chunk 0
    #pragma unroll
    for (int j = 0; j < 8; j++) af4[j] = __ldg((const float4*)(arow) + j);
    #pragma unroll
    for (int it = 0; it < 16; it++) {
        const float* wp = W1n + (size_t)(db + it * 4) * DIM + e0 + eb;
        bf[2 * it] = __ldg(wp);
        bf[2 * it + 1] = __ldg(wp + DIM);
    }
    // ---- S(0): convert+store chunk 0 into buffer 0
    {
        char* bufp = smem;
        #pragma unroll
        for (int j = 0; j < 8; j++) {
            float av[4] = {af4[j].x, af4[j].y, af4[j].z, af4[j].w};
            #pragma unroll
            for (int q = 0; q < 4; q += 2) {
                int d = dh + j * 4 + q;
                float a0 = s_drug[d] * av[q];
                float a1 = s_drug[d + 1] * av[q + 1];
                __half h0 = __float2half_rn(a0), h1 = __float2half_rn(a1);
                float l0 = a0 - __half2float(h0), l1 = a1 - __half2float(h1);
                *(__half2*)(bufp + A_HI + ka * ROWB + d * 2) = __halves2half2(h0, h1);
                *(__half2*)(bufp + A_LO + ka * ROWB + d * 2) =
                    __halves2half2(__float2half_rn(l0), __float2half_rn(l1));
            }
        }
        #pragma unroll
        for (int it = 0; it < 16; it++) {
            int dd = db + it * 4;
            float w0 = bf[2 * it], w1 = bf[2 * it + 1];
            __half h0 = __float2half_rn(w0), h1 = __float2half_rn(w1);
            float l0 = w0 - __half2float(h0), l1 = w1 - __half2float(h1);
            *(__half2*)(bufp + B_HI + eb * ROWB + dd * 2) = __halves2half2(h0, h1);
            *(__half2*)(bufp + B_LO + eb * ROWB + dd * 2) =
                __halves2half2(__float2half_rn(l0), __float2half_rn(l1));
        }
    }

    float c[2][8][4];
    #pragma unroll
    for (int mt = 0; mt < 2; mt++)
        #pragma unroll
        for (int nt = 0; nt < 8; nt++)
            #pragma unroll
            for (int q = 0; q < 4; q++) c[mt][nt][q] = 0.f;

    for (int ch = 0; ch < 4; ch++) {
        // ---- P(ch+1): prefetch next chunk into regs (before the MMA burst)
        if (ch < 3) {
            int dcn = (ch + 1) * 64;
            #pragma unroll
            for (int j = 0; j < 8; j++)
                af4[j] = __ldg((const float4*)(arow + dcn) + j);
            #pragma unroll
            for (int it = 0; it < 16; it++) {
                const float* wp = W1n + (size_t)(dcn + db + it * 4) * DIM + e0 + eb;
                bf[2 * it] = __ldg(wp);
                bf[2 * it + 1] = __ldg(wp + DIM);
            }
        }
        __syncthreads();   // buffer (ch&1) fully staged by all warps

        // ---- MMA burst on buffer ch&1
        uint32_t bofs = (uint32_t)(ch & 1) * BUFSZ;
        uint32_t a_off = a_base + bofs;
        uint32_t b_off = b_base + bofs;
        #pragma unroll
        for (int ks = 0; ks < 4; ks++) {
            uint32_t kb = ks * 32;
            uint32_t ah[2][4], al[2][4], bb[4][4];
            ldmx4(ah[0], a_off + kb);
            ldmx4(ah[1], a_off + 16 * ROWB + kb);
            #pragma unroll
            for (int np = 0; np < 4; np++)
                ldmx4(bb[np], b_off + np * 16 * ROWB + kb);
            #pragma unroll
            for (int np = 0; np < 4; np++) {
                mma16816(c[0][2 * np], ah[0], bb[np][0], bb[np][1]);
                mma16816(c[0][2 * np + 1], ah[0], bb[np][2], bb[np][3]);
                mma16816(c[1][2 * np], ah[1], bb[np][0], bb[np][1]);
                mma16816(c[1][2 * np + 1], ah[1], bb[np][2], bb[np][3]);
            }
            ldmx4(al[0], a_off + LO_OFF + kb);
            ldmx4(al[1], a_off + LO_OFF + 16 * ROWB + kb);
            #pragma unroll
            for (int np = 0; np < 4; np++) {
                mma16816(c[0][2 * np], al[0], bb[np][0], bb[np][1]);
                mma16816(c[0][2 * np + 1], al[0], bb[np][2], bb[np][3]);
                mma16816(c[1][2 * np], al[1], bb[np][0], bb[np][1]);
                mma16816(c[1][2 * np + 1], al[1], bb[np][2], bb[np][3]);
            }
            #pragma unroll
            for (int np = 0; np < 4; np++)
                ldmx4(bb[np], b_off + LO_OFF + np * 16 * ROWB + kb);
            #pragma unroll
            for (int np = 0; np < 4; np++) {
                mma16816(c[0][2 * np], ah[0], bb[np][0], bb[np][1]);
                mma16816(c[0][2 * np + 1], ah[0], bb[np][2], bb[np][3]);
                mma16816(c[1][2 * np], ah[1], bb[np][0], bb[np][1]);
                mma16816(c[1][2 * np + 1], ah[1], bb[np][2], bb[np][3]);
            }
        }

        // ---- fused w2 row sums (overlaps tensor drain)
        #pragma unroll
        for (int j = 0; j < 4; j++) {
            int row = wid * 16 + ch * 4 + j;
            const float4* rp =
                reinterpret_cast<const float4*>(W2n + (size_t)(e0 + row) * DIM);
            float4 a = __ldg(rp + lane);
            float4 b = __ldg(rp + lane + 32);
            float s = (a.x + a.y + a.z + a.w) + (b.x + b.y + b.z + b.w);
            #pragma unroll
            for (int m = 16; m; m >>= 1) s += __shfl_xor_sync(0xffffffffu, s, m);
            if (lane == 0) s_w2[row] = s;
        }

        // ---- S(ch+1): convert+store next chunk into buffer (ch+1)&1
        if (ch < 3) {
            char* bufp = smem + ((ch + 1) & 1) * BUFSZ;
            #pragma unroll
            for (int j = 0; j < 8; j++) {
                float av[4] = {af4[j].x, af4[j].y, af4[j].z, af4[j].w};
                int dcn = (ch + 1) * 64;
                #pragma unroll
                for (int q = 0; q < 4; q += 2) {
                    int d = dh + j * 4 + q;
                    float a0 = s_drug[dcn + d] * av[q];
                    float a1 = s_drug[dcn + d + 1] * av[q + 1];
                    __half h0 = __float2half_rn(a0), h1 = __float2half_rn(a1);
                    float l0 = a0 - __half2float(h0), l1 = a1 - __half2float(h1);
                    *(__half2*)(bufp + A_HI + ka * ROWB + d * 2) =
                        __halves2half2(h0, h1);
                    *(__half2*)(bufp + A_LO + ka * ROWB + d * 2) =
                        __halves2half2(__float2half_rn(l0), __float2half_rn(l1));
                }
            }
            #pragma unroll
            for (int it = 0; it < 16; it++) {
                int dd = db + it * 4;
                float w0 = bf[2 * it], w1 = bf[2 * it + 1];
                __half h0 = __float2half_rn(w0), h1 = __float2half_rn(w1);
                float l0 = w0 - __half2float(h0), l1 = w1 - __half2float(h1);
                *(__half2*)(bufp + B_HI + eb * ROWB + dd * 2) = __halves2half2(h0, h1);
                *(__half2*)(bufp + B_LO + eb * ROWB + dd * 2) =
                    __halves2half2(__float2half_rn(l0), __float2half_rn(l1));
            }
        }
    }
    __syncthreads();

    // ---- epilogue: +b1, relu, dot w2sum; deterministic reduction
    float lg[2][2] = {{0.f, 0.f}, {0.f, 0.f}};
    #pragma unroll
    for (int mt = 0; mt < 2; mt++) {
        int r0 = m0 + mt * 16 + g;
        #pragma unroll
        for (int nt = 0; nt < 8; nt++) {
            int ecl = n0 + nt * 8 + tg * 2;
            float w0 = s_w2[ecl], w1 = s_w2[ecl + 1];
            float2 b00 = *(const float2*)(b1p + (size_t)r0 * DIM + e0 + ecl);
            float2 b01 = *(const float2*)(b1p + (size_t)(r0 + 8) * DIM + e0 + ecl);
            lg[mt][0] += fmaxf(c[mt][nt][0] + b00.x, 0.f) * w0 +
                         fmaxf(c[mt][nt][1] + b00.y, 0.f) * w1;
            lg[mt][1] += fmaxf(c[mt][nt][2] + b01.x, 0.f) * w0 +
                         fmaxf(c[mt][nt][3] + b01.y, 0.f) * w1;
        }
    }
    #pragma unroll
    for (int mt = 0; mt < 2; mt++)
        #pragma unroll
        for (int h = 0; h < 2; h++) {
            float v = lg[mt][h];
            v += __shfl_xor_sync(0xffffffffu, v, 1);
            v += __shfl_xor_sync(0xffffffffu, v, 2);
            if (tg == 0)
                atomicAdd(&s_lp[m0 + mt * 16 + h * 8 + g], v);  // 2 contributors
        }
    __syncthreads();
    if (tid < KNB) g_lpart[n * 256 + eh * 128 + tid] = s_lp[tid];
}

// ---------------- k3: softmax + weighted entity gather (4-way k-sliced) -------
__global__ void __launch_bounds__(1024) k_softgather(
    const int* __restrict__ adj_tail, const float* __restrict__ ent_table) {
    __shared__ float s_logit[KNB];
    __shared__ int s_tail[KNB];
    __shared__ float s_red[32];
    __shared__ float s_scalar;
    __shared__ float s_acc[1024];
    int n = blockIdx.x, tid = threadIdx.x;
    int wid = tid >> 5, lane = tid & 31;

    if (tid < KNB) {
        s_logit[tid] = g_lpart[n * 256 + tid] + g_lpart[n * 256 + 128 + tid] +
                       g_b2sum[tid];
        s_tail[tid] = adj_tail[n * KNB + tid];
    }
    __syncthreads();

    float v = (tid < KNB) ? s_logit[tid] : -1e30f;
    #pragma unroll
    for (int m = 16; m; m >>= 1) v = fmaxf(v, __shfl_xor_sync(0xffffffffu, v, m));
    if (lane == 0) s_red[wid] = v;
    __syncthreads();
    if (tid == 0) {
        float mm = s_red[0];
        #pragma unroll
        for (int i = 1; i < 32; i++) mm = fmaxf(mm, s_red[i]);
        s_scalar = mm;
    }
    __syncthreads();
    float mm = s_scalar;
    float ev = (tid < KNB) ? expf(s_logit[tid] - mm) : 0.f;
    float sv = ev;
    #pragma unroll
    for (int m = 16; m; m >>= 1) sv += __shfl_xor_sync(0xffffffffu, sv, m);
    if (lane == 0) s_red[wid] = sv;
    __syncthreads();
    if (tid == 0) {
        float ss = 0.f;
        #pragma unroll
        for (int i = 0; i < 32; i++) ss += s_red[i];
        s_scalar = 1.f / ss;
    }
    __syncthreads();
    if (tid < KNB) s_logit[tid] = ev * s_scalar;
    __syncthreads();

    int d = tid & 255, sl = tid >> 8;
    float wacc = 0.f;
    #pragma unroll 8
    for (int k = sl * 32; k < sl * 32 + 32; k++)
        wacc += s_logit[k] * __ldg(&ent_table[(size_t)s_tail[k] * DIM + d]);
    s_acc[tid] = wacc;
    __syncthreads();
    if (tid < 256)
        g_weighted[n * DIM + tid] =
            (s_acc[tid] + s_acc[tid + 256]) + (s_acc[tid + 512] + s_acc[tid + 768]);
}

// ---------------- k4: x = relu([weighted, drug] @ lin_w^T + lin_b) ------------
__global__ void __launch_bounds__(256) k_linear(
    const int* __restrict__ drug_name, const float* __restrict__ drug_table,
    const float* __restrict__ lin_w, const float* __restrict__ lin_b) {
    __shared__ float s_in[3][512];
    __shared__ float s_w[256][33];
    int tid = threadIdx.x;
    int n0 = blockIdx.x * 3;

    #pragma unroll
    for (int p = 0; p < 6; p++) {
        int idx = tid + p * 256;
        int b = idx >> 9, i = idx & 511;
        float val;
        if (i < 256) val = g_weighted[(n0 + b) * DIM + i];
        else val = drug_table[drug_name[n0 + b] * DIM + (i - 256)];
        s_in[b][i] = val;
    }

    float acc[3] = {0.f, 0.f, 0.f};
    for (int i0 = 0; i0 < 512; i0 += 32) {
        __syncthreads();
        #pragma unroll
        for (int p = 0; p < 32; p++) {
            int j = (tid >> 5) + p * 8;
            int ii = tid & 31;
            s_w[j][ii] = lin_w[j * 512 + i0 + ii];
        }
        __syncthreads();
        #pragma unroll
        for (int ii = 0; ii < 32; ii++) {
            float w = s_w[tid][ii];
            #pragma unroll
            for (int b = 0; b < 3; b++) acc[b] += s_in[b][i0 + ii] * w;
        }
    }
    float bj = lin_b[tid];
    #pragma unroll
    for (int b = 0; b < 3; b++)
        g_x[(n0 + b) * DIM + tid] = fmaxf(acc[b] + bj, 0.f);
}

// ---------------- k4b: deterministic BN statistics ----------------------------
__global__ void __launch_bounds__(256) k_bnstat() {
    __shared__ float ss[256], sq[256];
    int j = blockIdx.x, tid = threadIdx.x;
    float s = 0.f, q = 0.f;
    for (int nn = tid; nn < N_DRUG; nn += 256) {
        float v = g_x[nn * DIM + j];
        s += v;
        q += v * v;
    }
    ss[tid] = s;
    sq[tid] = q;
    __syncthreads();
    #pragma unroll
    for (int off = 128; off; off >>= 1) {
        if (tid < off) {
            ss[tid] += ss[tid + off];
            sq[tid] += sq[tid + off];
        }
        __syncthreads();
    }
    if (tid == 0) {
        g_sum[j] = ss[0];
        g_sumsq[j] = sq[0];
    }
}

// ---------------- k5: BatchNorm finalize --------------------------------------
__global__ void k_bn(const float* __restrict__ gamma, const float* __restrict__ beta,
                     float* __restrict__ out) {
    int n = blockIdx.x, j = threadIdx.x;
    const float inv_n = 1.f / 846.f;
    float mean = g_sum[j] * inv_n;
    float var = g_sumsq[j] * inv_n - mean * mean;
    float rstd = rsqrtf(var + 1e-5f);
    out[n * DIM + j] = gamma[j] * (g_x[n * DIM + j] - mean) * rstd + beta[j];
}

// ---------------- launch -------------------------------------------------------
extern "C" void kernel_launch(void* const* d_in, const int* in_sizes, int n_in,
                              void* d_out, int out_size) {
    const int* drug_name = (const int*)d_in[0];
    const int* adj_tail = (const int*)d_in[1];
    const int* adj_rel = (const int*)d_in[2];
    const float* drug_table = (const float*)d_in[3];
    const float* rela_table = (const float*)d_in[4];
    const float* ent_table = (const float*)d_in[5];
    const float* W1 = (const float*)d_in[6];
    const float* b1 = (const float*)d_in[7];
    const float* W2 = (const float*)d_in[8];
    const float* b2 = (const float*)d_in[9];
    const float* lin_w = (const float*)d_in[10];
    const float* lin_b = (const float*)d_in[11];
    const float* gamma = (const float*)d_in[12];
    const float* beta = (const float*)d_in[13];
    float* out = (float*)d_out;

    cudaFuncSetAttribute(k_logits, cudaFuncAttributeMaxDynamicSharedMemorySize,
                         SMEM_TOTAL);

    k_init<<<1, 256>>>(b2);
    dim3 grid_l(N_DRUG, 2);
    k_logits<<<grid_l, 256, SMEM_TOTAL>>>(drug_name, adj_rel, drug_table,
                                          rela_table, W1, b1, W2);
    k_softgather<<<N_DRUG, 1024>>>(adj_tail, ent_table);
    k_linear<<<282, 256>>>(drug_name, drug_table, lin_w, lin_b);
    k_bnstat<<<256, 256>>>();
    k_bn<<<N_DRUG, 256>>>(gamma, beta, out);
}